// round 3
// baseline (speedup 1.0000x reference)
#include <cuda_runtime.h>
#include <math.h>
#include <stdint.h>

#define TT 512
#define BB 64
#define DD 512
#define HH 512
#define GG 2048
#define KTOT 1024

typedef unsigned long long u64;

// ---------------- device scratch ----------------
__device__ float g_W[(size_t)GG * KTOT];        // 8 MB normalized weights
__device__ float g_zx[(size_t)TT * GG * BB];    // 256 MB x-projection (+bias)
__device__ float g_h[2][(size_t)HH * BB];       // h double buffer, [col][b]
__device__ unsigned g_bar_cnt;                  // grid barrier count (returns to 0)
__device__ unsigned g_bar_gen;                  // generation (monotonic)

// ---------------- f32x2 helpers ----------------
__device__ __forceinline__ u64 pack2(float x, float y) {
    u64 r; asm("mov.b64 %0, {%1, %2};" : "=l"(r) : "f"(x), "f"(y)); return r;
}
__device__ __forceinline__ void fma2(u64& d, u64 a, u64 b) {
    asm("fma.rn.f32x2 %0, %1, %2, %0;" : "+l"(d) : "l"(a), "l"(b));
}
__device__ __forceinline__ float2 unpack2(u64 v) {
    float2 f; asm("mov.b64 {%0, %1}, %2;" : "=f"(f.x), "=f"(f.y) : "l"(v)); return f;
}

// ---------------- cp.async (L2-only) ----------------
__device__ __forceinline__ void cp_async16(void* smem_dst, const void* gsrc) {
    unsigned s = (unsigned)__cvta_generic_to_shared(smem_dst);
    asm volatile("cp.async.cg.shared.global [%0], [%1], 16;" :: "r"(s), "l"(gsrc));
}
#define CP_COMMIT() asm volatile("cp.async.commit_group;" ::: "memory")
#define CP_WAIT0()  asm volatile("cp.async.wait_group 0;" ::: "memory")

__device__ __forceinline__ unsigned ld_acq(unsigned* p) {
    unsigned v;
    asm volatile("ld.acquire.gpu.u32 %0, [%1];" : "=r"(v) : "l"(p) : "memory");
    return v;
}

__device__ __forceinline__ void grid_barrier(int nblocks) {
    __syncthreads();
    if (threadIdx.x == 0) {
        unsigned gen = ld_acq(&g_bar_gen);          // snapshot BEFORE arriving
        __threadfence();                            // publish h writes
        unsigned arrived = atomicAdd(&g_bar_cnt, 1u);
        if (arrived == (unsigned)(nblocks - 1)) {
            atomicExch(&g_bar_cnt, 0u);
            __threadfence();
            atomicAdd(&g_bar_gen, 1u);
        } else {
            while (ld_acq(&g_bar_gen) == gen) { __nanosleep(64); }
        }
        __threadfence();
    }
    __syncthreads();
}

__device__ __forceinline__ float sigf(float x) { return 1.0f / (1.0f + expf(-x)); }

// ============================================================================
// Phase 1: weight norm. W[r,:] = g[r] * v[r,:] / ||v[r,:]||
// ============================================================================
__global__ __launch_bounds__(256) void qlstm_wnorm(const float* __restrict__ v,
                                                   const float* __restrict__ g) {
    int r = blockIdx.x;
    const float* vr = v + (size_t)r * KTOT;
    float s = 0.0f;
    for (int k = threadIdx.x; k < KTOT; k += 256) { float x = vr[k]; s += x * x; }
    __shared__ float red[256];
    red[threadIdx.x] = s;
    __syncthreads();
    for (int off = 128; off > 0; off >>= 1) {
        if (threadIdx.x < off) red[threadIdx.x] += red[threadIdx.x + off];
        __syncthreads();
    }
    float scale = g[r] * rsqrtf(red[0]);
    for (int k = threadIdx.x; k < KTOT; k += 256)
        g_W[(size_t)r * KTOT + k] = vr[k] * scale;
}

// ============================================================================
// Phase 2: zx[t][r][b] = sum_d X[t,b,d] * W[r][d] + bias[r]
// CTA tile 128r x 64b x 16k, 256 threads, thread tile 8r x 4b, f32x2 across b.
// ============================================================================
__global__ __launch_bounds__(256) void qlstm_gemm_x(const float* __restrict__ X,
                                                    const float* __restrict__ bias) {
    __shared__ u64   Asd[128 * 17];   // duplicated (w,w), row pad 17 -> no conflicts
    __shared__ float Bs[16 * 64];     // [k][b]

    const int rt  = blockIdx.x * 128;
    const int t   = blockIdx.y;
    const int tid = threadIdx.x;
    const int rg  = tid >> 4;         // 0..15 -> 8 rows each
    const int ng  = tid & 15;         // 0..15 -> 4 batches each
    const int b0  = ng * 4;

    u64 acc[8][2];
    #pragma unroll
    for (int i = 0; i < 8; i++) { acc[i][0] = 0ULL; acc[i][1] = 0ULL; }

    for (int kt = 0; kt < DD; kt += 16) {
        __syncthreads();
        #pragma unroll
        for (int u = 0; u < 2; u++) {
            int idx = tid + u * 256;            // 0..511
            int r = idx >> 2, kq = (idx & 3) << 2;
            float4 va = *(const float4*)(g_W + (size_t)(rt + r) * KTOT + kt + kq);
            Asd[r * 17 + kq + 0] = pack2(va.x, va.x);
            Asd[r * 17 + kq + 1] = pack2(va.y, va.y);
            Asd[r * 17 + kq + 2] = pack2(va.z, va.z);
            Asd[r * 17 + kq + 3] = pack2(va.w, va.w);
        }
        {
            int n = tid >> 2, kq = (tid & 3) << 2;
            float4 vb = *(const float4*)(X + ((size_t)t * BB + n) * DD + kt + kq);
            Bs[(kq + 0) * 64 + n] = vb.x;
            Bs[(kq + 1) * 64 + n] = vb.y;
            Bs[(kq + 2) * 64 + n] = vb.z;
            Bs[(kq + 3) * 64 + n] = vb.w;
        }
        __syncthreads();

        #pragma unroll
        for (int kk = 0; kk < 16; kk++) {
            u64 bb0 = *(const u64*)&Bs[kk * 64 + b0];
            u64 bb1 = *(const u64*)&Bs[kk * 64 + b0 + 2];
            #pragma unroll
            for (int i = 0; i < 8; i++) {
                u64 a = Asd[(rg * 8 + i) * 17 + kk];
                fma2(acc[i][0], a, bb0);
                fma2(acc[i][1], a, bb1);
            }
        }
    }

    #pragma unroll
    for (int i = 0; i < 8; i++) {
        int r = rt + rg * 8 + i;
        float bi = bias[r];
        float2 p0 = unpack2(acc[i][0]);
        float2 p1 = unpack2(acc[i][1]);
        *(float4*)(g_zx + ((size_t)t * GG + r) * BB + b0) =
            make_float4(p0.x + bi, p0.y + bi, p1.x + bi, p1.y + bi);
    }
}

// ============================================================================
// Phase 3: persistent recurrence. 128 CTAs x 256 thr, CTA owns h-cols
// [4*bc, 4*bc+4) -> 16 gate rows. Weights dup in smem; h via cp.async chunks.
// ============================================================================
#define P3_NCTA 128
#define SM_BYTES (65536 + 65536 + 4096)

__global__ __launch_bounds__(256) void qlstm_recur(float* __restrict__ out, int out_size) {
    extern __shared__ unsigned char smraw[];
    u64*   Ws2 = (u64*)smraw;                        // [16][512] dup pairs (64KB)
    float* hs  = (float*)(smraw + 65536);            // 2 x [128k][64b]   (64KB)
    float* zs  = (float*)(smraw + 131072);           // [16][64]          (4KB)

    const int tid = threadIdx.x;
    const int bc  = blockIdx.x;
    const int c0  = bc * 4;

    // load + duplicate recurrent weight slice
    #pragma unroll
    for (int u = 0; u < 32; u++) {
        int idx = tid + u * 256;          // 0..8191
        int lr = idx >> 9, k = idx & 511;
        int gr = (lr >> 2) * 512 + c0 + (lr & 3);
        float w = g_W[(size_t)gr * KTOT + 512 + k];
        Ws2[lr * 512 + k] = pack2(w, w);
    }
    // zero h buffer 0 (every replay) + c state in register
    const int ep_j = tid >> 6, ep_b = tid & 63;
    g_h[0][(size_t)(c0 + ep_j) * BB + ep_b] = 0.0f;
    float creg = 0.0f, hlast = 0.0f;
    __threadfence();
    grid_barrier(P3_NCTA);

    const int kp  = tid >> 7;             // K half
    const int lt  = tid & 127;
    const int rg  = lt >> 4;              // 0..7 -> rows lr0, lr0+1
    const int bg  = lt & 15;
    const int lr0 = rg * 2;
    const int b0  = bg * 4;
    const int gr0 = ((lr0)     >> 2) * 512 + c0 + ((lr0)     & 3);
    const int gr1 = ((lr0 + 1) >> 2) * 512 + c0 + ((lr0 + 1) & 3);

    for (int s = 0; s < TT; s++) {
        const float* hsrc = g_h[s & 1];

        // prefetch h chunk 0 (32KB)
        #pragma unroll
        for (int u = 0; u < 8; u++) {
            int idx = tid + u * 256;
            cp_async16(hs + idx * 4, hsrc + idx * 4);
        }
        CP_COMMIT();

        u64 acc00, acc01, acc10, acc11;
        {
            const float* zxp = g_zx + (size_t)s * GG * BB;
            if (kp == 0) {
                float4 z0 = *(const float4*)(zxp + (size_t)gr0 * BB + b0);
                float4 z1 = *(const float4*)(zxp + (size_t)gr1 * BB + b0);
                acc00 = pack2(z0.x, z0.y); acc01 = pack2(z0.z, z0.w);
                acc10 = pack2(z1.x, z1.y); acc11 = pack2(z1.z, z1.w);
            } else {
                acc00 = acc01 = acc10 = acc11 = 0ULL;
            }
        }

        for (int ch = 0; ch < 4; ch++) {
            CP_WAIT0();
            __syncthreads();
            if (ch < 3) {
                const float* src = hsrc + (ch + 1) * 8192;
                float* dst = hs + ((ch + 1) & 1) * 8192;
                #pragma unroll
                for (int u = 0; u < 8; u++) {
                    int idx = tid + u * 256;
                    cp_async16(dst + idx * 4, src + idx * 4);
                }
                CP_COMMIT();
            }
            const float* hb = hs + (ch & 1) * 8192 + kp * 64 * 64;
            const u64* w0p = Ws2 + lr0 * 512 + ch * 128 + kp * 64;
            const u64* w1p = w0p + 512;
            #pragma unroll 8
            for (int kc = 0; kc < 64; kc++) {
                u64 a0 = w0p[kc];
                u64 a1 = w1p[kc];
                u64 h0 = *(const u64*)(hb + kc * 64 + b0);
                u64 h1 = *(const u64*)(hb + kc * 64 + b0 + 2);
                fma2(acc00, a0, h0); fma2(acc01, a0, h1);
                fma2(acc10, a1, h0); fma2(acc11, a1, h1);
            }
        }

        // combine kp halves in smem
        float2* z2 = (float2*)zs;
        if (kp) {
            z2[lr0 * 32 + bg * 2]           = unpack2(acc00);
            z2[lr0 * 32 + bg * 2 + 1]       = unpack2(acc01);
            z2[(lr0 + 1) * 32 + bg * 2]     = unpack2(acc10);
            z2[(lr0 + 1) * 32 + bg * 2 + 1] = unpack2(acc11);
        }
        __syncthreads();
        if (!kp) {
            float2 p00 = z2[lr0 * 32 + bg * 2];
            float2 p01 = z2[lr0 * 32 + bg * 2 + 1];
            float2 p10 = z2[(lr0 + 1) * 32 + bg * 2];
            float2 p11 = z2[(lr0 + 1) * 32 + bg * 2 + 1];
            float2 a;
            a = unpack2(acc00); zs[lr0 * 64 + b0 + 0] = a.x + p00.x; zs[lr0 * 64 + b0 + 1] = a.y + p00.y;
            a = unpack2(acc01); zs[lr0 * 64 + b0 + 2] = a.x + p01.x; zs[lr0 * 64 + b0 + 3] = a.y + p01.y;
            a = unpack2(acc10); zs[(lr0 + 1) * 64 + b0 + 0] = a.x + p10.x; zs[(lr0 + 1) * 64 + b0 + 1] = a.y + p10.y;
            a = unpack2(acc11); zs[(lr0 + 1) * 64 + b0 + 2] = a.x + p11.x; zs[(lr0 + 1) * 64 + b0 + 3] = a.y + p11.y;
        }
        __syncthreads();

        // gate epilogue: thread (ep_j, ep_b)
        float zf = zs[(0 * 4 + ep_j) * 64 + ep_b];
        float zi = zs[(1 * 4 + ep_j) * 64 + ep_b];
        float zu = zs[(2 * 4 + ep_j) * 64 + ep_b];
        float zo = zs[(3 * 4 + ep_j) * 64 + ep_b];
        float fg = sigf(zf), ig = sigf(zi), ug = tanhf(zu), og = sigf(zo);
        creg = fg * creg + ig * ug;
        float hv = og * tanhf(creg);
        hlast = hv;
        g_h[(s + 1) & 1][(size_t)(c0 + ep_j) * BB + ep_b] = hv;
        out[(size_t)s * BB * HH + (size_t)ep_b * HH + c0 + ep_j] = hv;

        grid_barrier(P3_NCTA);
    }

    // hx, cx tails if the output buffer includes them
    size_t TBH = (size_t)TT * BB * HH;
    if ((size_t)out_size >= TBH + 2 * (size_t)BB * HH) {
        out[TBH + (size_t)ep_b * HH + c0 + ep_j] = hlast;
        out[TBH + (size_t)BB * HH + (size_t)ep_b * HH + c0 + ep_j] = creg;
    }
}

extern "C" void kernel_launch(void* const* d_in, const int* in_sizes, int n_in,
                              void* d_out, int out_size) {
    const float* X  = (const float*)d_in[0];
    const float* v  = (const float*)d_in[1];
    const float* g  = (const float*)d_in[2];
    const float* b  = (const float*)d_in[3];
    float* out = (float*)d_out;

    cudaFuncSetAttribute(qlstm_recur, cudaFuncAttributeMaxDynamicSharedMemorySize, SM_BYTES);

    qlstm_wnorm<<<GG, 256>>>(v, g);
    qlstm_gemm_x<<<dim3(GG / 128, TT), 256>>>(X, b);
    qlstm_recur<<<P3_NCTA, 256, SM_BYTES>>>(out, out_size);
}

// round 4
// speedup vs baseline: 1.1597x; 1.1597x over previous
#include <cuda_runtime.h>
#include <math.h>
#include <stdint.h>

#define TT 512
#define BB 64
#define DD 512
#define HH 512
#define GG 2048
#define KTOT 1024

typedef unsigned long long u64;

// ---------------- device scratch ----------------
__device__ float g_W[(size_t)GG * KTOT];        // 8 MB normalized weights
__device__ float g_zx[(size_t)TT * GG * BB];    // 256 MB x-projection (+bias)
__device__ float g_h[2][(size_t)HH * BB];       // h double buffer, [col][b]
__device__ unsigned g_bar_cnt;
__device__ unsigned g_bar_gen;

// ---------------- f32x2 helpers ----------------
__device__ __forceinline__ u64 pack2(float x, float y) {
    u64 r; asm("mov.b64 %0, {%1, %2};" : "=l"(r) : "f"(x), "f"(y)); return r;
}
__device__ __forceinline__ void fma2(u64& d, u64 a, u64 b) {
    asm("fma.rn.f32x2 %0, %1, %2, %0;" : "+l"(d) : "l"(a), "l"(b));
}
__device__ __forceinline__ float2 unpack2(u64 v) {
    float2 f; asm("mov.b64 {%0, %1}, %2;" : "=f"(f.x), "=f"(f.y) : "l"(v)); return f;
}

// ---------------- cp.async (L2-only) ----------------
__device__ __forceinline__ void cp_async16(void* smem_dst, const void* gsrc) {
    unsigned s = (unsigned)__cvta_generic_to_shared(smem_dst);
    asm volatile("cp.async.cg.shared.global [%0], [%1], 16;" :: "r"(s), "l"(gsrc));
}
#define CP_COMMIT() asm volatile("cp.async.commit_group;" ::: "memory")
#define CP_WAIT0()  asm volatile("cp.async.wait_group 0;" ::: "memory")

__device__ __forceinline__ unsigned ld_acq(unsigned* p) {
    unsigned v;
    asm volatile("ld.acquire.gpu.u32 %0, [%1];" : "=r"(v) : "l"(p) : "memory");
    return v;
}

__device__ __forceinline__ void grid_barrier(int nblocks) {
    __syncthreads();
    if (threadIdx.x == 0) {
        unsigned gen = ld_acq(&g_bar_gen);          // snapshot BEFORE arriving
        __threadfence();                            // publish h writes
        unsigned arrived = atomicAdd(&g_bar_cnt, 1u);
        if (arrived == (unsigned)(nblocks - 1)) {
            atomicExch(&g_bar_cnt, 0u);
            __threadfence();
            atomicAdd(&g_bar_gen, 1u);
        } else {
            while (ld_acq(&g_bar_gen) == gen) { __nanosleep(32); }
        }
        __threadfence();
    }
    __syncthreads();
}

__device__ __forceinline__ float sigf(float x) { return 1.0f / (1.0f + expf(-x)); }

// ============================================================================
// Phase 1: weight norm
// ============================================================================
__global__ __launch_bounds__(256) void qlstm_wnorm(const float* __restrict__ v,
                                                   const float* __restrict__ g) {
    int r = blockIdx.x;
    const float* vr = v + (size_t)r * KTOT;
    float s = 0.0f;
    for (int k = threadIdx.x; k < KTOT; k += 256) { float x = vr[k]; s += x * x; }
    __shared__ float red[256];
    red[threadIdx.x] = s;
    __syncthreads();
    for (int off = 128; off > 0; off >>= 1) {
        if (threadIdx.x < off) red[threadIdx.x] += red[threadIdx.x + off];
        __syncthreads();
    }
    float scale = g[r] * rsqrtf(red[0]);
    for (int k = threadIdx.x; k < KTOT; k += 256)
        g_W[(size_t)r * KTOT + k] = vr[k] * scale;
}

// ============================================================================
// Phase 2: zx[t][r][b] = X @ Wx^T + bias.  128r x 64b x 16k tiles, LDS.128.
// ============================================================================
__global__ __launch_bounds__(256) void qlstm_gemm_x(const float* __restrict__ X,
                                                    const float* __restrict__ bias) {
    __shared__ u64   Asd[128 * 18];   // dup (w,w), pad 18 -> LDS.128-aligned rows
    __shared__ float Bs[16 * 64];     // [k][b]

    const int rt  = blockIdx.x * 128;
    const int t   = blockIdx.y;
    const int tid = threadIdx.x;
    const int rg  = tid >> 4;         // 8 rows each
    const int ng  = tid & 15;         // 4 batches each
    const int b0  = ng * 4;

    u64 acc[8][2];
    #pragma unroll
    for (int i = 0; i < 8; i++) { acc[i][0] = 0ULL; acc[i][1] = 0ULL; }

    for (int kt = 0; kt < DD; kt += 16) {
        __syncthreads();
        #pragma unroll
        for (int u = 0; u < 2; u++) {
            int idx = tid + u * 256;
            int r = idx >> 2, kq = (idx & 3) << 2;
            float4 va = *(const float4*)(g_W + (size_t)(rt + r) * KTOT + kt + kq);
            Asd[r * 18 + kq + 0] = pack2(va.x, va.x);
            Asd[r * 18 + kq + 1] = pack2(va.y, va.y);
            Asd[r * 18 + kq + 2] = pack2(va.z, va.z);
            Asd[r * 18 + kq + 3] = pack2(va.w, va.w);
        }
        {
            int n = tid >> 2, kq = (tid & 3) << 2;
            float4 vb = *(const float4*)(X + ((size_t)t * BB + n) * DD + kt + kq);
            Bs[(kq + 0) * 64 + n] = vb.x;
            Bs[(kq + 1) * 64 + n] = vb.y;
            Bs[(kq + 2) * 64 + n] = vb.z;
            Bs[(kq + 3) * 64 + n] = vb.w;
        }
        __syncthreads();

        #pragma unroll
        for (int kk = 0; kk < 16; kk += 2) {
            ulonglong2 bq0 = *(const ulonglong2*)&Bs[kk * 64 + b0];        // kk
            ulonglong2 bq1 = *(const ulonglong2*)&Bs[(kk + 1) * 64 + b0];  // kk+1
            #pragma unroll
            for (int i = 0; i < 8; i++) {
                ulonglong2 aq = *(const ulonglong2*)&Asd[(rg * 8 + i) * 18 + kk];
                fma2(acc[i][0], aq.x, bq0.x); fma2(acc[i][1], aq.x, bq0.y);
                fma2(acc[i][0], aq.y, bq1.x); fma2(acc[i][1], aq.y, bq1.y);
            }
        }
    }

    #pragma unroll
    for (int i = 0; i < 8; i++) {
        int r = rt + rg * 8 + i;
        float bi = bias[r];
        float2 p0 = unpack2(acc[i][0]);
        float2 p1 = unpack2(acc[i][1]);
        *(float4*)(g_zx + ((size_t)t * GG + r) * BB + b0) =
            make_float4(p0.x + bi, p0.y + bi, p1.x + bi, p1.y + bi);
    }
}

// ============================================================================
// Phase 3: persistent recurrence. 128 CTAs x 256 thr; 4-way k-split, 4r x 4b
// thread tiles, LDS.128 operand loads, zx prefetched into smem.
// ============================================================================
#define P3_NCTA 128
// smem: Ws2 64KB | hs 64KB | zxs 8KB | zsp 16KB
#define OFF_HS  65536
#define OFF_ZXS 131072
#define OFF_ZSP 139264
#define SM_BYTES (139264 + 16384)

__global__ __launch_bounds__(256) void qlstm_recur(float* __restrict__ out, int out_size) {
    extern __shared__ unsigned char smraw[];
    u64*   Ws2 = (u64*)smraw;                       // [16][512] dup pairs
    float* hs  = (float*)(smraw + OFF_HS);          // 2 x [128k][64b]
    float* zxs = (float*)(smraw + OFF_ZXS);         // 2 x [16][64]
    float* zsp = (float*)(smraw + OFF_ZSP);         // [4 kp][16][64]

    const int tid = threadIdx.x;
    const int bc  = blockIdx.x;
    const int c0  = bc * 4;

    // load + duplicate recurrent weight slice (16 rows x 512 k)
    #pragma unroll
    for (int u = 0; u < 32; u++) {
        int idx = tid + u * 256;
        int lr = idx >> 9, k = idx & 511;
        int gr = (lr >> 2) * 512 + c0 + (lr & 3);
        float w = g_W[(size_t)gr * KTOT + 512 + k];
        Ws2[lr * 512 + k] = pack2(w, w);
    }

    // zx prefetch helper mapping: thread -> (lr, 4 floats)
    const int pf_lr = tid >> 4;
    const int pf_b  = (tid & 15) * 4;
    const int pf_gr = (pf_lr >> 2) * 512 + c0 + (pf_lr & 3);

    // prefetch zx[0] into zxs buffer 0
    cp_async16(zxs + pf_lr * 64 + pf_b,
               g_zx + (size_t)pf_gr * BB + pf_b);
    CP_COMMIT();

    // zero h buffer 0 (each replay) + c state
    const int ep_j = tid >> 6, ep_b = tid & 63;
    g_h[0][(size_t)(c0 + ep_j) * BB + ep_b] = 0.0f;
    float creg = 0.0f, hlast = 0.0f;
    CP_WAIT0();
    __threadfence();
    grid_barrier(P3_NCTA);

    const int kp  = tid >> 6;            // 0..3 k-quarter (within each 128-chunk)
    const int lt  = tid & 63;
    const int rg  = lt >> 4;             // 0..3 -> rows lr0..lr0+3
    const int bg  = lt & 15;
    const int lr0 = rg * 4;
    const int b0  = bg * 4;

    for (int s = 0; s < TT; s++) {
        const float* hsrc = g_h[s & 1];

        // issue h chunk 0 (32KB) + zx[s+1] prefetch
        #pragma unroll
        for (int u = 0; u < 8; u++) {
            int idx = tid + u * 256;
            cp_async16(hs + idx * 4, hsrc + idx * 4);
        }
        if (s + 1 < TT) {
            cp_async16(zxs + ((s + 1) & 1) * 1024 + pf_lr * 64 + pf_b,
                       g_zx + ((size_t)(s + 1) * GG + pf_gr) * BB + pf_b);
        }
        CP_COMMIT();

        // init accumulators: kp==0 carries zx (from smem), others zero
        u64 acc[4][2];
        if (kp == 0) {
            const float* zb = zxs + (s & 1) * 1024;
            #pragma unroll
            for (int r = 0; r < 4; r++) {
                float4 z = *(const float4*)(zb + (lr0 + r) * 64 + b0);
                acc[r][0] = pack2(z.x, z.y);
                acc[r][1] = pack2(z.z, z.w);
            }
        } else {
            #pragma unroll
            for (int r = 0; r < 4; r++) { acc[r][0] = 0ULL; acc[r][1] = 0ULL; }
        }

        // K loop: 4 chunks of 128 cols, double buffered; kp quarter = 32 cols
        for (int ch = 0; ch < 4; ch++) {
            CP_WAIT0();
            __syncthreads();
            if (ch < 3) {
                const float* src = hsrc + (ch + 1) * 8192;
                float* dst = hs + ((ch + 1) & 1) * 8192;
                #pragma unroll
                for (int u = 0; u < 8; u++) {
                    int idx = tid + u * 256;
                    cp_async16(dst + idx * 4, src + idx * 4);
                }
                CP_COMMIT();
            }
            const float* hb = hs + (ch & 1) * 8192 + kp * 32 * 64;
            const u64* wb = Ws2 + ch * 128 + kp * 32;
            #pragma unroll 8
            for (int kc = 0; kc < 32; kc += 2) {
                ulonglong2 h0 = *(const ulonglong2*)(hb + kc * 64 + b0);
                ulonglong2 h1 = *(const ulonglong2*)(hb + (kc + 1) * 64 + b0);
                #pragma unroll
                for (int r = 0; r < 4; r++) {
                    ulonglong2 wq = *(const ulonglong2*)&wb[(lr0 + r) * 512 + kc];
                    fma2(acc[r][0], wq.x, h0.x); fma2(acc[r][1], wq.x, h0.y);
                    fma2(acc[r][0], wq.y, h1.x); fma2(acc[r][1], wq.y, h1.y);
                }
            }
        }

        // write partials: zsp[kp][row][b]
        {
            float* zp = zsp + kp * 1024;
            #pragma unroll
            for (int r = 0; r < 4; r++) {
                float2 a0 = unpack2(acc[r][0]);
                float2 a1 = unpack2(acc[r][1]);
                *(float4*)&zp[(lr0 + r) * 64 + b0] = make_float4(a0.x, a0.y, a1.x, a1.y);
            }
        }
        __syncthreads();

        // gate epilogue: thread (ep_j, ep_b); rows = gate*4 + ep_j
        float z[4];
        #pragma unroll
        for (int gidx = 0; gidx < 4; gidx++) {
            int row = gidx * 4 + ep_j;
            z[gidx] = zsp[0 * 1024 + row * 64 + ep_b]
                    + zsp[1 * 1024 + row * 64 + ep_b]
                    + zsp[2 * 1024 + row * 64 + ep_b]
                    + zsp[3 * 1024 + row * 64 + ep_b];
        }
        float fg = sigf(z[0]), ig = sigf(z[1]), ug = tanhf(z[2]), og = sigf(z[3]);
        creg = fg * creg + ig * ug;
        float hv = og * tanhf(creg);
        hlast = hv;
        g_h[(s + 1) & 1][(size_t)(c0 + ep_j) * BB + ep_b] = hv;
        out[((size_t)s * BB + ep_b) * HH + c0 + ep_j] = hv;

        grid_barrier(P3_NCTA);
    }

    size_t TBH = (size_t)TT * BB * HH;
    if ((size_t)out_size >= TBH + 2 * (size_t)BB * HH) {
        out[TBH + (size_t)ep_b * HH + c0 + ep_j] = hlast;
        out[TBH + (size_t)BB * HH + (size_t)ep_b * HH + c0 + ep_j] = creg;
    }
}

extern "C" void kernel_launch(void* const* d_in, const int* in_sizes, int n_in,
                              void* d_out, int out_size) {
    const float* X  = (const float*)d_in[0];
    const float* v  = (const float*)d_in[1];
    const float* g  = (const float*)d_in[2];
    const float* b  = (const float*)d_in[3];
    float* out = (float*)d_out;

    cudaFuncSetAttribute(qlstm_recur, cudaFuncAttributeMaxDynamicSharedMemorySize, SM_BYTES);

    qlstm_wnorm<<<GG, 256>>>(v, g);
    qlstm_gemm_x<<<dim3(GG / 128, TT), 256>>>(X, b);
    qlstm_recur<<<P3_NCTA, 256, SM_BYTES>>>(out, out_size);
}

// round 5
// speedup vs baseline: 1.5788x; 1.3614x over previous
#include <cuda_runtime.h>
#include <math.h>
#include <stdint.h>

#define TT 512
#define BB 64
#define DD 512
#define HH 512
#define GG 2048
#define KTOT 1024

typedef unsigned long long u64;

// ---------------- device scratch ----------------
__device__ float g_W[(size_t)GG * KTOT];        // 8 MB normalized weights
__device__ float g_zx[(size_t)TT * GG * BB];    // 256 MB x-projection (+bias)
__device__ float g_h[2][(size_t)HH * BB];       // h double buffer, [col][b]
__device__ unsigned g_bar_cnt;
__device__ unsigned g_bar_gen;

// ---------------- f32x2 helpers ----------------
__device__ __forceinline__ u64 pack2(float x, float y) {
    u64 r; asm("mov.b64 %0, {%1, %2};" : "=l"(r) : "f"(x), "f"(y)); return r;
}
__device__ __forceinline__ void fma2(u64& d, u64 a, u64 b) {
    asm("fma.rn.f32x2 %0, %1, %2, %0;" : "+l"(d) : "l"(a), "l"(b));
}
__device__ __forceinline__ float2 unpack2(u64 v) {
    float2 f; asm("mov.b64 {%0, %1}, %2;" : "=f"(f.x), "=f"(f.y) : "l"(v)); return f;
}

// ---------------- cp.async (L2-only) ----------------
__device__ __forceinline__ void cp_async16(void* smem_dst, const void* gsrc) {
    unsigned s = (unsigned)__cvta_generic_to_shared(smem_dst);
    asm volatile("cp.async.cg.shared.global [%0], [%1], 16;" :: "r"(s), "l"(gsrc));
}
#define CP_COMMIT() asm volatile("cp.async.commit_group;" ::: "memory")
#define CP_WAIT0()  asm volatile("cp.async.wait_group 0;" ::: "memory")

__device__ __forceinline__ unsigned ld_acq(unsigned* p) {
    unsigned v;
    asm volatile("ld.acquire.gpu.u32 %0, [%1];" : "=r"(v) : "l"(p) : "memory");
    return v;
}

__device__ __forceinline__ void grid_barrier(int nblocks) {
    __syncthreads();
    if (threadIdx.x == 0) {
        unsigned gen = ld_acq(&g_bar_gen);
        __threadfence();
        unsigned arrived = atomicAdd(&g_bar_cnt, 1u);
        if (arrived == (unsigned)(nblocks - 1)) {
            atomicExch(&g_bar_cnt, 0u);
            __threadfence();
            atomicAdd(&g_bar_gen, 1u);
        } else {
            while (ld_acq(&g_bar_gen) == gen) { __nanosleep(32); }
        }
        __threadfence();
    }
    __syncthreads();
}

__device__ __forceinline__ float sigf(float x) { return 1.0f / (1.0f + expf(-x)); }

// ============================================================================
// Phase 1: weight norm
// ============================================================================
__global__ __launch_bounds__(256) void qlstm_wnorm(const float* __restrict__ v,
                                                   const float* __restrict__ g) {
    int r = blockIdx.x;
    const float* vr = v + (size_t)r * KTOT;
    float s = 0.0f;
    for (int k = threadIdx.x; k < KTOT; k += 256) { float x = vr[k]; s += x * x; }
    __shared__ float red[256];
    red[threadIdx.x] = s;
    __syncthreads();
    for (int off = 128; off > 0; off >>= 1) {
        if (threadIdx.x < off) red[threadIdx.x] += red[threadIdx.x + off];
        __syncthreads();
    }
    float scale = g[r] * rsqrtf(red[0]);
    for (int k = threadIdx.x; k < KTOT; k += 256)
        g_W[(size_t)r * KTOT + k] = vr[k] * scale;
}

// ============================================================================
// Phase 2: zx = X @ Wx^T + bias.  CTA 128r x 128n (2 timesteps), 256 thr,
// thread tile 8r x 8n, A transposed non-dup in smem, reg packs, f32x2 on n.
// ============================================================================
#define AST_PAD 132
#define BSS_PAD 132

__global__ __launch_bounds__(256) void qlstm_gemm_x(const float* __restrict__ X,
                                                    const float* __restrict__ bias) {
    __shared__ float Ast[16 * AST_PAD];   // [k][r] transposed
    __shared__ float Bs[16 * BSS_PAD];    // [k][n]

    const int rt  = blockIdx.x * 128;
    const int nt  = blockIdx.y * 128;
    const int tid = threadIdx.x;
    const int rg  = tid >> 4;     // 0..15
    const int ng  = tid & 15;     // 0..15
    const int r0  = rg * 8;
    const int n0  = ng * 8;

    u64 acc[8][4];
    #pragma unroll
    for (int i = 0; i < 8; i++)
        #pragma unroll
        for (int j = 0; j < 4; j++) acc[i][j] = 0ULL;

    for (int kt = 0; kt < DD; kt += 16) {
        __syncthreads();
        #pragma unroll
        for (int u = 0; u < 2; u++) {
            int idx = tid + u * 256;
            int r = idx >> 2, kq = (idx & 3) << 2;
            float4 va = *(const float4*)(g_W + (size_t)(rt + r) * KTOT + kt + kq);
            Ast[(kq + 0) * AST_PAD + r] = va.x;
            Ast[(kq + 1) * AST_PAD + r] = va.y;
            Ast[(kq + 2) * AST_PAD + r] = va.z;
            Ast[(kq + 3) * AST_PAD + r] = va.w;
        }
        #pragma unroll
        for (int u = 0; u < 2; u++) {
            int idx = tid + u * 256;
            int n = idx >> 2, kq = (idx & 3) << 2;
            float4 vb = *(const float4*)(X + (size_t)(nt + n) * DD + kt + kq);
            Bs[(kq + 0) * BSS_PAD + n] = vb.x;
            Bs[(kq + 1) * BSS_PAD + n] = vb.y;
            Bs[(kq + 2) * BSS_PAD + n] = vb.z;
            Bs[(kq + 3) * BSS_PAD + n] = vb.w;
        }
        __syncthreads();

        #pragma unroll
        for (int kk = 0; kk < 16; kk++) {
            ulonglong2 b01 = *(const ulonglong2*)&Bs[kk * BSS_PAD + n0];
            ulonglong2 b23 = *(const ulonglong2*)&Bs[kk * BSS_PAD + n0 + 4];
            float4 w0 = *(const float4*)&Ast[kk * AST_PAD + r0];
            float4 w1 = *(const float4*)&Ast[kk * AST_PAD + r0 + 4];
            float wv[8] = {w0.x, w0.y, w0.z, w0.w, w1.x, w1.y, w1.z, w1.w};
            #pragma unroll
            for (int i = 0; i < 8; i++) {
                u64 wd = pack2(wv[i], wv[i]);
                fma2(acc[i][0], wd, b01.x); fma2(acc[i][1], wd, b01.y);
                fma2(acc[i][2], wd, b23.x); fma2(acc[i][3], wd, b23.y);
            }
        }
    }

    const int t  = blockIdx.y * 2 + (n0 >> 6);
    const int b0 = n0 & 63;
    #pragma unroll
    for (int i = 0; i < 8; i++) {
        int r = rt + r0 + i;
        float bi = bias[r];
        float2 p0 = unpack2(acc[i][0]);
        float2 p1 = unpack2(acc[i][1]);
        float2 p2 = unpack2(acc[i][2]);
        float2 p3 = unpack2(acc[i][3]);
        float* dst = g_zx + ((size_t)t * GG + r) * BB + b0;
        *(float4*)dst       = make_float4(p0.x + bi, p0.y + bi, p1.x + bi, p1.y + bi);
        *(float4*)(dst + 4) = make_float4(p2.x + bi, p2.y + bi, p3.x + bi, p3.y + bi);
    }
}

// ============================================================================
// Phase 3: persistent recurrence. 128 CTAs x 256 thr = 8 warps.
// warp = k-split (64 k), thread tile 8r x 4b (rows interleaved by rgi),
// weights non-dup float in smem, each warp cp.asyncs exactly its own h slice.
// ============================================================================
#define P3_NCTA 128
#define WS_PAD 516
#define OFF_HS  (16 * WS_PAD * 4)            // 33024
#define OFF_ZSP (OFF_HS + 131072)            // 164096
#define OFF_ZXS (OFF_ZSP + 32768)            // 196864
#define SM_BYTES (OFF_ZXS + 8192)            // 205056

__global__ __launch_bounds__(256) void qlstm_recur(float* __restrict__ out, int out_size) {
    extern __shared__ unsigned char smraw[];
    float* Wsf = (float*)smraw;                     // [16][516] non-dup
    float* hs  = (float*)(smraw + OFF_HS);          // [512][64]
    float* zsp = (float*)(smraw + OFF_ZSP);         // [8 ks][16][64]
    float* zxs = (float*)(smraw + OFF_ZXS);         // [2][16][64]

    const int tid = threadIdx.x;
    const int bc  = blockIdx.x;
    const int c0  = bc * 4;

    // load weight slice (non-duplicated)
    #pragma unroll
    for (int u = 0; u < 32; u++) {
        int idx = tid + u * 256;
        int lr = idx >> 9, k = idx & 511;
        int gr = (lr >> 2) * 512 + c0 + (lr & 3);
        Wsf[lr * WS_PAD + k] = g_W[(size_t)gr * KTOT + 512 + k];
    }

    const int pf_lr = tid >> 4;
    const int pf_b  = (tid & 15) * 4;
    const int pf_gr = (pf_lr >> 2) * 512 + c0 + (pf_lr & 3);

    // prefetch zx[0]
    cp_async16(zxs + pf_lr * 64 + pf_b, g_zx + (size_t)pf_gr * BB + pf_b);
    CP_COMMIT();

    const int ep_j = tid >> 6, ep_b = tid & 63;
    g_h[0][(size_t)(c0 + ep_j) * BB + ep_b] = 0.0f;
    float creg = 0.0f, hlast = 0.0f;
    CP_WAIT0();
    __threadfence();
    grid_barrier(P3_NCTA);

    const int ks    = tid >> 5;          // warp = k-split
    const int lane  = tid & 31;
    const int rgi   = (tid >> 4) & 1;    // row interleave bit
    const int b0    = (tid & 15) * 4;
    const int kbase = ks * 64;

    for (int s = 0; s < TT; s++) {
        const float* hsrc = g_h[s & 1];

        // zx[s+1] prefetch + own 16KB h slice (race-free: we consume only our own copies)
        if (s + 1 < TT)
            cp_async16(zxs + ((s + 1) & 1) * 1024 + pf_lr * 64 + pf_b,
                       g_zx + ((size_t)(s + 1) * GG + pf_gr) * BB + pf_b);
        {
            const float* src = hsrc + kbase * 64;
            float* dst = hs + kbase * 64;
            #pragma unroll
            for (int u = 0; u < 32; u++) {
                int idx = lane + u * 32;          // 0..1023 float4 slots
                cp_async16(dst + idx * 4, src + idx * 4);
            }
        }
        CP_COMMIT();
        CP_WAIT0();

        u64 acc[8][2];
        #pragma unroll
        for (int r = 0; r < 8; r++) { acc[r][0] = 0ULL; acc[r][1] = 0ULL; }

        const float* hbase = hs + kbase * 64 + b0;
        const float* wbase = Wsf + rgi * WS_PAD + kbase;

        #pragma unroll 4
        for (int kb = 0; kb < 16; kb++) {
            ulonglong2 hq[4];
            #pragma unroll
            for (int j = 0; j < 4; j++)
                hq[j] = *(const ulonglong2*)(hbase + (kb * 4 + j) * 64);
            #pragma unroll
            for (int rr = 0; rr < 8; rr++) {
                float4 wv = *(const float4*)(wbase + rr * 2 * WS_PAD + kb * 4);
                u64 w0 = pack2(wv.x, wv.x), w1 = pack2(wv.y, wv.y);
                u64 w2 = pack2(wv.z, wv.z), w3 = pack2(wv.w, wv.w);
                fma2(acc[rr][0], w0, hq[0].x); fma2(acc[rr][1], w0, hq[0].y);
                fma2(acc[rr][0], w1, hq[1].x); fma2(acc[rr][1], w1, hq[1].y);
                fma2(acc[rr][0], w2, hq[2].x); fma2(acc[rr][1], w2, hq[2].y);
                fma2(acc[rr][0], w3, hq[3].x); fma2(acc[rr][1], w3, hq[3].y);
            }
        }

        // write k-split partials
        #pragma unroll
        for (int rr = 0; rr < 8; rr++) {
            int lr = rr * 2 + rgi;
            float2 a = unpack2(acc[rr][0]);
            float2 c = unpack2(acc[rr][1]);
            *(float4*)&zsp[(ks * 16 + lr) * 64 + b0] = make_float4(a.x, a.y, c.x, c.y);
        }
        __syncthreads();

        // gate epilogue
        float z[4];
        #pragma unroll
        for (int gi = 0; gi < 4; gi++) {
            int row = gi * 4 + ep_j;
            float ssum = zxs[(s & 1) * 1024 + row * 64 + ep_b];
            #pragma unroll
            for (int q = 0; q < 8; q++)
                ssum += zsp[(q * 16 + row) * 64 + ep_b];
            z[gi] = ssum;
        }
        float fg = sigf(z[0]), ig = sigf(z[1]), ug = tanhf(z[2]), og = sigf(z[3]);
        creg = fg * creg + ig * ug;
        float hv = og * tanhf(creg);
        hlast = hv;
        g_h[(s + 1) & 1][(size_t)(c0 + ep_j) * BB + ep_b] = hv;
        out[((size_t)s * BB + ep_b) * HH + c0 + ep_j] = hv;

        grid_barrier(P3_NCTA);
    }

    size_t TBH = (size_t)TT * BB * HH;
    if ((size_t)out_size >= TBH + 2 * (size_t)BB * HH) {
        out[TBH + (size_t)ep_b * HH + c0 + ep_j] = hlast;
        out[TBH + (size_t)BB * HH + (size_t)ep_b * HH + c0 + ep_j] = creg;
    }
}

extern "C" void kernel_launch(void* const* d_in, const int* in_sizes, int n_in,
                              void* d_out, int out_size) {
    const float* X  = (const float*)d_in[0];
    const float* v  = (const float*)d_in[1];
    const float* g  = (const float*)d_in[2];
    const float* b  = (const float*)d_in[3];
    float* out = (float*)d_out;

    cudaFuncSetAttribute(qlstm_recur, cudaFuncAttributeMaxDynamicSharedMemorySize, SM_BYTES);

    qlstm_wnorm<<<GG, 256>>>(v, g);
    qlstm_gemm_x<<<dim3(GG / 128, TT / 2), 256>>>(X, b);
    qlstm_recur<<<P3_NCTA, 256, SM_BYTES>>>(out, out_size);
}